// round 1
// baseline (speedup 1.0000x reference)
#include <cuda_runtime.h>

#define N_BATCH 64
#define L_LEN   512
#define F_LEN   2048

// Scratch: per-n running max of (min over f of Chebyshev dist), as float bits.
// Distances are >= 0, so integer atomicMax on the bit pattern is order-correct.
__device__ int g_scratch[N_BATCH];

__global__ void init_kernel() {
    g_scratch[threadIdx.x] = 0;  // 0.0f
}

// One warp per 32 queries (same n). Each lane owns one (n,l) query and scans
// all 2048 candidate points of B with L-infinity distance, keeping the min.
// Then warp-max over the 32 lanes (different l), atomicMax into per-n slot.
__global__ __launch_bounds__(32) void dist_kernel(const float* __restrict__ A,
                                                  const float* __restrict__ B) {
    const int w = blockIdx.x;          // 0..1023
    const int n = w >> 4;              // 16 warps per n (512 l / 32 lanes)
    const int l = ((w & 15) << 5) + threadIdx.x;

    const float2 a = *reinterpret_cast<const float2*>(A + (size_t)(n * L_LEN + l) * 2);
    const float4* __restrict__ Bx = reinterpret_cast<const float4*>(B);          // B[0][f]
    const float4* __restrict__ By = reinterpret_cast<const float4*>(B + F_LEN);  // B[1][f]

    // 4 independent accumulators -> ILP against lat-4 pipes
    float m0 = 1e30f, m1 = 1e30f, m2 = 1e30f, m3 = 1e30f;

    #pragma unroll 4
    for (int i = 0; i < F_LEN / 4; ++i) {
        const float4 bx = __ldg(&Bx[i]);   // uniform address -> L1 broadcast
        const float4 by = __ldg(&By[i]);
        m0 = fminf(m0, fmaxf(fabsf(a.x - bx.x), fabsf(a.y - by.x)));
        m1 = fminf(m1, fmaxf(fabsf(a.x - bx.y), fabsf(a.y - by.y)));
        m2 = fminf(m2, fmaxf(fabsf(a.x - bx.z), fabsf(a.y - by.z)));
        m3 = fminf(m3, fmaxf(fabsf(a.x - bx.w), fabsf(a.y - by.w)));
    }

    float best = fminf(fminf(m0, m1), fminf(m2, m3));   // min over f for this l

    #pragma unroll
    for (int off = 16; off; off >>= 1)                  // max over the 32 l's
        best = fmaxf(best, __shfl_xor_sync(0xffffffffu, best, off));

    if (threadIdx.x == 0)
        atomicMax(&g_scratch[n], __float_as_int(best));
}

// out[n] = sigmoid(10*d) * sigmoid(-10*d) evaluated once per batch row.
__global__ void finish_kernel(float* __restrict__ out) {
    const int n = threadIdx.x;
    const float x  = __int_as_float(g_scratch[n]);
    const float s1 = 1.0f / (1.0f + expf(-10.0f * x));
    const float s2 = 1.0f / (1.0f + expf( 10.0f * x));
    out[n] = s1 * s2;
}

extern "C" void kernel_launch(void* const* d_in, const int* in_sizes, int n_in,
                              void* d_out, int out_size) {
    const float* A = (const float*)d_in[0];   // (64, 512, 2) fp32
    const float* B = (const float*)d_in[1];   // (1, 2, 2048) fp32
    float* out = (float*)d_out;               // (64, 1) fp32

    init_kernel<<<1, N_BATCH>>>();
    dist_kernel<<<(N_BATCH * L_LEN) / 32, 32>>>(A, B);
    finish_kernel<<<1, N_BATCH>>>(out);
}